// round 14
// baseline (speedup 1.0000x reference)
#include <cuda_runtime.h>
#include <cstdint>
#include <float.h>

#define N_   2
#define K_   2048
#define DIN_ 1024
#define H_   16
#define D_   64
#define HD_  1024
#define QSCALE 0.18033688011112043f   // 0.125 * log2(e)

// ---------------- device scratch: separated hi/lo planes ----------------
__device__ __align__(16) uint32_t g_wbh[4][512][1024];  // weights hi (B)
__device__ __align__(16) uint32_t g_wbl[4][512][1024];  // weights lo
__device__ __align__(16) uint32_t g_qph[32][2048][32];  // q hi (scaled), d-pair packed
__device__ __align__(16) uint32_t g_qpl[32][2048][32];
__device__ __align__(16) uint32_t g_kph[32][2048][32];  // k hi
__device__ __align__(16) uint32_t g_kpl[32][2048][32];
__device__ __align__(16) uint32_t g_vh[32][64][1024];   // v hi [nh][d][jpair]
__device__ __align__(16) uint32_t g_vl[32][64][1024];
__device__ __align__(16) float    g_v [32][2048][64];   // v fp32 (for repack)
__device__ __align__(16) uint32_t g_yah[4096][512];     // attn out hi (outproj A)
__device__ __align__(16) uint32_t g_yal[4096][512];
__device__ uint32_t g_mb[(size_t)N_ * K_ * 64];         // packed mask bits

// ---------------- helpers ----------------
__device__ __forceinline__ void bsplit(float x0, float x1, uint32_t& h, uint32_t& l) {
    const uint32_t u0 = __float_as_uint(x0), u1 = __float_as_uint(x1);
    h = __byte_perm(u0, u1, 0x7632);
    const float r0 = x0 - __uint_as_float(u0 & 0xffff0000u);
    const float r1 = x1 - __uint_as_float(u1 & 0xffff0000u);
    asm("cvt.rn.bf16x2.f32 %0, %1, %2;" : "=r"(l) : "f"(r1), "f"(r0));
}
__device__ __forceinline__ void mma_bf16(float* c, const uint32_t* a, const uint32_t* b) {
    asm volatile(
        "mma.sync.aligned.m16n8k16.row.col.f32.bf16.bf16.f32 "
        "{%0,%1,%2,%3}, {%4,%5,%6,%7}, {%8,%9}, {%0,%1,%2,%3};"
        : "+f"(c[0]), "+f"(c[1]), "+f"(c[2]), "+f"(c[3])
        : "r"(a[0]), "r"(a[1]), "r"(a[2]), "r"(a[3]), "r"(b[0]), "r"(b[1]));
}
__device__ __forceinline__ void ldm4(uint32_t* r, uint32_t addr) {
    asm volatile("ldmatrix.sync.aligned.m8n8.x4.shared.b16 {%0,%1,%2,%3}, [%4];"
                 : "=r"(r[0]), "=r"(r[1]), "=r"(r[2]), "=r"(r[3]) : "r"(addr));
}
__device__ __forceinline__ uint32_t smem_u32(const void* p) {
    uint32_t a;
    asm("{ .reg .u64 t; cvta.to.shared.u64 t, %1; cvt.u32.u64 %0, t; }" : "=r"(a) : "l"(p));
    return a;
}
__device__ __forceinline__ float ex2f(float x) {
    float r; asm("ex2.approx.f32 %0, %1;" : "=f"(r) : "f"(x)); return r;
}
__device__ __forceinline__ void cpa(uint32_t dst, const void* src) {
    asm volatile("cp.async.cg.shared.global [%0], [%1], 16;" :: "r"(dst), "l"(src));
}
#define CP_COMMIT() asm volatile("cp.async.commit_group;" ::: "memory")
#define CP_WAIT0()  asm volatile("cp.async.wait_group 0;" ::: "memory")

// ---------------- prep kernels ----------------
__global__ __launch_bounds__(256) void mask_pack(const int* __restrict__ mask) {
    const int idx = blockIdx.x * 256 + threadIdx.x;
    const uint32_t b = __ballot_sync(0xffffffffu, mask[idx] != 0);
    if ((threadIdx.x & 31) == 0) g_mb[idx >> 5] = b;
}

__global__ __launch_bounds__(256) void split_w(const float* __restrict__ wq,
    const float* __restrict__ wk, const float* __restrict__ wv, const float* __restrict__ wp) {
    const int z = blockIdx.y, kp = blockIdx.x, ng = threadIdx.x * 4;
    float4 r0, r1;
    if (z < 3) {
        const float* s = (z == 0) ? wq : (z == 1) ? wk : wv;
        const size_t a0 = (size_t)(ng >> 6) * (DIN_ * D_) + (size_t)(2 * kp) * D_ + (ng & 63);
        r0 = *(const float4*)(s + a0);
        r1 = *(const float4*)(s + a0 + D_);
    } else {
        const size_t a0 = (size_t)(2 * kp) * DIN_ + ng;
        r0 = *(const float4*)(wp + a0);
        r1 = *(const float4*)(wp + a0 + DIN_);
    }
    uint32_t h[4], l[4];
    bsplit(r0.x, r1.x, h[0], l[0]);
    bsplit(r0.y, r1.y, h[1], l[1]);
    bsplit(r0.z, r1.z, h[2], l[2]);
    bsplit(r0.w, r1.w, h[3], l[3]);
    *(uint4*)&g_wbh[z][kp][ng] = make_uint4(h[0], h[1], h[2], h[3]);
    *(uint4*)&g_wbl[z][kp][ng] = make_uint4(l[0], l[1], l[2], l[3]);
}

__global__ __launch_bounds__(256) void repack_v() {
    __shared__ float t[64][68];
    const int nh = blockIdx.y, jt = blockIdx.x, tid = threadIdx.x;
#pragma unroll
    for (int i = 0; i < 4; i++) {
        const int flat = tid + i * 256, tok = flat & 63, d4 = (flat >> 6) * 4;
        *(float4*)&t[tok][d4] = *(const float4*)&g_v[nh][jt * 64 + tok][d4];
    }
    __syncthreads();
    const int jp = tid & 31, dg = tid >> 5;
#pragma unroll
    for (int i = 0; i < 8; i++) {
        const int d = dg * 8 + i;
        uint32_t hh, ll;
        bsplit(t[2 * jp][d], t[2 * jp + 1][d], hh, ll);
        g_vh[nh][d][jt * 32 + jp] = hh;
        g_vl[nh][d][jt * 32 + jp] = ll;
    }
}

// ---------------- GEMM: R9 structure (k16, 2-buf, LDG+STS), inline A split ----------------
// smem words: A [buf][hl][128][12] = 6144, B [buf][hl][8 kp][136] = 4352 -> 42KB static
// mode 0: grid (32,8,3)  A = fp32 query/key/value (inline bsplit), B = g_wb[z]
//         out: z0 -> g_qp planes (scaled), z1 -> g_kp planes, z2 -> g_v fp32
// mode 1: grid (32,8,1)  A = g_yah/g_yal planes, B = g_wb[3], out fp32
#define AW(b,hl) (((b)*2+(hl))*1536)
#define BW(b,hl) (6144 + ((b)*2+(hl))*1088)

__global__ __launch_bounds__(256) void gemm_mma(int mode,
    const float* __restrict__ xq, const float* __restrict__ xk, const float* __restrict__ xv,
    const float* __restrict__ bq, const float* __restrict__ bk,
    const float* __restrict__ bv, const float* __restrict__ bp,
    float* __restrict__ outp)
{
    __shared__ uint32_t gsm[10496];
    const uint32_t sb = smem_u32(gsm);

    const int tid = threadIdx.x, wid = tid >> 5, lane = tid & 31;
    const int gid = lane >> 2, tig = lane & 3, wm = wid >> 2, wn = wid & 3;
    const int m0 = blockIdx.x * 128, by = blockIdx.y;
    const int z = (mode == 0) ? blockIdx.z : 3;

    const float* Xf = (z == 0) ? xq : (z == 1) ? xk : xv;   // mode 0 A source (fp32)
    const uint32_t* Bh = &g_wbh[z][0][0];
    const uint32_t* Bl = &g_wbl[z][0][0];
    const float* bias = (z == 0) ? bq : (z == 1) ? bk : (z == 2) ? bv : bp;

    // loader mappings
    const int ar = tid >> 1, t1 = tid & 1;            // A: row, half (kp 4t1..4t1+3)
    const int bkk = tid >> 5, bn4 = (tid & 31) << 2;  // B: kp row, 4-word n group
    const int bcol = by * 128 + bn4;

    float acc[4][4][4] = {};
    float4 af0, af1;          // mode 0: fp32 A prefetch
    uint4 ap0, ap1;           // mode 1: plane A prefetch (hi, lo)
    uint4 bh4, bl4;

    // ---- prologue: load + store chunk 0 ----
    if (mode == 0) {
        af0 = *(const float4*)(Xf + (size_t)(m0 + ar) * DIN_ + t1 * 8);
        af1 = *(const float4*)(Xf + (size_t)(m0 + ar) * DIN_ + t1 * 8 + 4);
    } else {
        ap0 = *(const uint4*)&g_yah[m0 + ar][t1 * 4];
        ap1 = *(const uint4*)&g_yal[m0 + ar][t1 * 4];
    }
    bh4 = *(const uint4*)&Bh[(size_t)bkk * 1024 + bcol];
    bl4 = *(const uint4*)&Bl[(size_t)bkk * 1024 + bcol];

    {
        uint32_t h[4], l[4];
        if (mode == 0) {
            bsplit(af0.x, af0.y, h[0], l[0]);
            bsplit(af0.z, af0.w, h[1], l[1]);
            bsplit(af1.x, af1.y, h[2], l[2]);
            bsplit(af1.z, af1.w, h[3], l[3]);
        } else {
            h[0] = ap0.x; h[1] = ap0.y; h[2] = ap0.z; h[3] = ap0.w;
            l[0] = ap1.x; l[1] = ap1.y; l[2] = ap1.z; l[3] = ap1.w;
        }
        *(uint4*)&gsm[AW(0,0) + ar * 12 + t1 * 4] = make_uint4(h[0], h[1], h[2], h[3]);
        *(uint4*)&gsm[AW(0,1) + ar * 12 + t1 * 4] = make_uint4(l[0], l[1], l[2], l[3]);
        *(uint4*)&gsm[BW(0,0) + bkk * 136 + bn4] = bh4;
        *(uint4*)&gsm[BW(0,1) + bkk * 136 + bn4] = bl4;
    }
    __syncthreads();

    for (int c = 0; c < 64; c++) {
        const int buf = c & 1;

        // prefetch chunk c+1 into registers (latency hidden under MMAs)
        if (c < 63) {
            const int kc = (c + 1) * 16;       // k offset (fp32 floats)
            const int kp0 = (c + 1) * 8;       // kpair offset (plane words)
            if (mode == 0) {
                af0 = *(const float4*)(Xf + (size_t)(m0 + ar) * DIN_ + kc + t1 * 8);
                af1 = *(const float4*)(Xf + (size_t)(m0 + ar) * DIN_ + kc + t1 * 8 + 4);
            } else {
                ap0 = *(const uint4*)&g_yah[m0 + ar][kp0 + t1 * 4];
                ap1 = *(const uint4*)&g_yal[m0 + ar][kp0 + t1 * 4];
            }
            bh4 = *(const uint4*)&Bh[(size_t)(kp0 + bkk) * 1024 + bcol];
            bl4 = *(const uint4*)&Bl[(size_t)(kp0 + bkk) * 1024 + bcol];
        }

        // ---- one k16 mma step ----
        uint32_t ah[4][4], al[4][4];
#pragma unroll
        for (int mt = 0; mt < 4; mt++) {
            const uint32_t off = (wm * 64 + mt * 16 + (lane & 15)) * 12 + (lane >> 4) * 4;
            ldm4(ah[mt], sb + (AW(buf,0) + off) * 4);
            ldm4(al[mt], sb + (AW(buf,1) + off) * 4);
        }
        uint32_t bh[4][2], bl[4][2];
#pragma unroll
        for (int nt = 0; nt < 4; nt++) {
            const int nc = wn * 32 + nt * 8 + gid;
            bh[nt][0] = gsm[BW(buf,0) + tig * 136 + nc];
            bh[nt][1] = gsm[BW(buf,0) + (tig + 4) * 136 + nc];
            bl[nt][0] = gsm[BW(buf,1) + tig * 136 + nc];
            bl[nt][1] = gsm[BW(buf,1) + (tig + 4) * 136 + nc];
        }
#pragma unroll
        for (int mt = 0; mt < 4; mt++)
#pragma unroll
            for (int nt = 0; nt < 4; nt++) {
                mma_bf16(acc[mt][nt], ah[mt], bh[nt]);
                mma_bf16(acc[mt][nt], al[mt], bh[nt]);
                mma_bf16(acc[mt][nt], ah[mt], bl[nt]);
            }

        // ---- store prefetched chunk into other buffer ----
        if (c < 63) {
            const int nb = buf ^ 1;
            uint32_t h[4], l[4];
            if (mode == 0) {
                bsplit(af0.x, af0.y, h[0], l[0]);
                bsplit(af0.z, af0.w, h[1], l[1]);
                bsplit(af1.x, af1.y, h[2], l[2]);
                bsplit(af1.z, af1.w, h[3], l[3]);
            } else {
                h[0] = ap0.x; h[1] = ap0.y; h[2] = ap0.z; h[3] = ap0.w;
                l[0] = ap1.x; l[1] = ap1.y; l[2] = ap1.z; l[3] = ap1.w;
            }
            *(uint4*)&gsm[AW(nb,0) + ar * 12 + t1 * 4] = make_uint4(h[0], h[1], h[2], h[3]);
            *(uint4*)&gsm[AW(nb,1) + ar * 12 + t1 * 4] = make_uint4(l[0], l[1], l[2], l[3]);
            *(uint4*)&gsm[BW(nb,0) + bkk * 136 + bn4] = bh4;
            *(uint4*)&gsm[BW(nb,1) + bkk * 136 + bn4] = bl4;
            __syncthreads();
        }
    }

    // ---- epilogue ----
#pragma unroll
    for (int mt = 0; mt < 4; mt++)
#pragma unroll
        for (int nt = 0; nt < 4; nt++) {
            const int ng = by * 128 + wn * 32 + nt * 8 + 2 * tig;
            const float b0 = bias[ng], b1 = bias[ng + 1];
#pragma unroll
            for (int half = 0; half < 2; half++) {
                const int m = m0 + wm * 64 + mt * 16 + gid + half * 8;
                float v0 = acc[mt][nt][half * 2 + 0] + b0;
                float v1 = acc[mt][nt][half * 2 + 1] + b1;
                if (mode == 1) {
                    *(float2*)(outp + (size_t)m * HD_ + ng) = make_float2(v0, v1);
                } else {
                    const int nn = m >> 11, kk = m & 2047, h = ng >> 6;
                    if (z == 2) {
                        *(float2*)&g_v[nn * 16 + h][kk][ng & 63] = make_float2(v0, v1);
                    } else {
                        if (z == 0) { v0 *= QSCALE; v1 *= QSCALE; }
                        uint32_t hh, ll;
                        bsplit(v0, v1, hh, ll);
                        const int dp = (ng >> 1) & 31;
                        if (z == 0) { g_qph[nn * 16 + h][kk][dp] = hh; g_qpl[nn * 16 + h][kk][dp] = ll; }
                        else        { g_kph[nn * 16 + h][kk][dp] = hh; g_kpl[nn * 16 + h][kk][dp] = ll; }
                    }
                }
            }
        }
}

// ---------------- flash attention: cp.async 2-buf pipeline (R13, unchanged) ----------------
// per-buf words: Kh[64][36]=2304, Kl 2304, Vh[64][36]=2304, Vl 2304 -> 9216
#define FBUF 9216
#define FLASH_SMEM (2 * FBUF * 4)

__global__ __launch_bounds__(256, 2) void flash_mma()
{
    extern __shared__ uint32_t sm[];
    const uint32_t sb = smem_u32(sm);

    const int qt = blockIdx.x, nh = blockIdx.y, n = nh >> 4, h = nh & 15;
    const int tid = threadIdx.x, w = tid >> 5, lane = tid & 31;
    const int gid = lane >> 2, tig = lane & 3, r0 = w * 16 + gid;

    // ---- stage Q planes (cp.async into buf0: Qh@0, Ql@4608) ----
    {
        const int qr = tid >> 1, qc = (tid & 1) * 16;
        const uint32_t dq = sb + (qr * 36 + qc) * 4;
#pragma unroll
        for (int i = 0; i < 4; i++) {
            cpa(dq + i * 16,            &g_qph[nh][qt * 128 + qr][qc + i * 4]);
            cpa(dq + 4608 * 4 + i * 16, &g_qpl[nh][qt * 128 + qr][qc + i * 4]);
        }
        CP_COMMIT();
    }
    CP_WAIT0();
    __syncthreads();

    uint32_t afh[4][4], afl[4][4];
    {
        const uint32_t off = (uint32_t)(w * 16 + (lane & 15)) * 36 + (lane >> 4) * 4;
#pragma unroll
        for (int sp = 0; sp < 4; sp++) {
            ldm4(afh[sp], sb + (off + sp * 8) * 4);
            ldm4(afl[sp], sb + (4608 + off + sp * 8) * 4);
        }
    }
    __syncthreads();   // all warps done reading Q staging before tile0 overwrite

    // cp.async tile loader mapping
    const int fj = tid >> 2, fq = (tid & 3) * 8;
    const uint32_t dK = sb + (fj * 36 + fq) * 4;
    const uint32_t dV = sb + (4608 + fj * 36 + fq) * 4;

#define FCP(kt, buf) do { \
    cpa(dK + (buf) * FBUF * 4,               &g_kph[nh][(kt) * 64 + fj][fq]); \
    cpa(dK + (buf) * FBUF * 4 + 16,          &g_kph[nh][(kt) * 64 + fj][fq + 4]); \
    cpa(dK + ((buf) * FBUF + 2304) * 4,      &g_kpl[nh][(kt) * 64 + fj][fq]); \
    cpa(dK + ((buf) * FBUF + 2304) * 4 + 16, &g_kpl[nh][(kt) * 64 + fj][fq + 4]); \
    cpa(dV + (buf) * FBUF * 4,               &g_vh[nh][fj][(kt) * 32 + fq]); \
    cpa(dV + (buf) * FBUF * 4 + 16,          &g_vh[nh][fj][(kt) * 32 + fq + 4]); \
    cpa(dV + ((buf) * FBUF + 2304) * 4,      &g_vl[nh][fj][(kt) * 32 + fq]); \
    cpa(dV + ((buf) * FBUF + 2304) * 4 + 16, &g_vl[nh][fj][(kt) * 32 + fq + 4]); \
    CP_COMMIT(); } while (0)

    FCP(0, 0);

    float o[8][4] = {};
    float ls0 = 0.f, ls1 = 0.f;
    const uint32_t* mr0 = g_mb + (size_t)(n * K_ + qt * 128 + r0) * 64;
    const uint32_t* mr1 = mr0 + 8 * 64;

    const uint32_t brow = (lane & 7) + ((lane & 16) ? 8u : 0u);
    const uint32_t bbyt = (lane & 8) ? 16u : 0u;

#pragma unroll 2
    for (int kt = 0; kt < 32; kt++) {
        const int buf = kt & 1;
        // mask prefetch first: LDG latency hides under QK MMAs
        const uint2 w0 = *(const uint2*)(mr0 + kt * 2);
        const uint2 w1 = *(const uint2*)(mr1 + kt * 2);
        CP_WAIT0();
        __syncthreads();
        if (kt + 1 < 32) { FCP(kt + 1, buf ^ 1); } else { CP_COMMIT(); }

        // S = Q K^T (3-term)
        float s[8][4] = {};
#pragma unroll
        for (int sp = 0; sp < 4; sp++) {
#pragma unroll
            for (int g = 0; g < 4; g++) {
                const uint32_t base = (buf * FBUF + (g * 16 + brow) * 36 + sp * 8) * 4 + bbyt;
                uint32_t kh4[4], kl4[4];
                ldm4(kh4, sb + base);
                ldm4(kl4, sb + 2304 * 4 + base);
#pragma unroll
                for (int t = 0; t < 2; t++) {
                    mma_bf16(s[g * 2 + t], afh[sp], kh4 + 2 * t);
                    mma_bf16(s[g * 2 + t], afl[sp], kh4 + 2 * t);
                    mma_bf16(s[g * 2 + t], afh[sp], kl4 + 2 * t);
                }
            }
        }

        // mask + exp2 (no-max softmax; scale folded into q)
#pragma unroll
        for (int nt = 0; nt < 8; nt++) {
            const int jb = nt * 8 + 2 * tig;
#pragma unroll
            for (int cc = 0; cc < 4; cc++) {
                const int j = jb + (cc & 1);
                const uint32_t word = (cc < 2) ? ((j < 32) ? w0.x : w0.y)
                                               : ((j < 32) ? w1.x : w1.y);
                s[nt][cc] = ((word >> (j & 31)) & 1u) ? 0.f : ex2f(s[nt][cc]);
            }
            ls0 += s[nt][0] + s[nt][1];
            ls1 += s[nt][2] + s[nt][3];
        }

        // O += P V (P frags in registers)
#pragma unroll
        for (int sp = 0; sp < 4; sp++) {
            uint32_t aph[4], apl[4];
            bsplit(s[2 * sp][0],     s[2 * sp][1],     aph[0], apl[0]);
            bsplit(s[2 * sp][2],     s[2 * sp][3],     aph[1], apl[1]);
            bsplit(s[2 * sp + 1][0], s[2 * sp + 1][1], aph[2], apl[2]);
            bsplit(s[2 * sp + 1][2], s[2 * sp + 1][3], aph[3], apl[3]);
#pragma unroll
            for (int g = 0; g < 4; g++) {
                const uint32_t base = (buf * FBUF + 4608 + (g * 16 + brow) * 36 + sp * 8) * 4 + bbyt;
                uint32_t vh4[4], vl4[4];
                ldm4(vh4, sb + base);
                ldm4(vl4, sb + 2304 * 4 + base);
#pragma unroll
                for (int t = 0; t < 2; t++) {
                    mma_bf16(o[g * 2 + t], aph, vh4 + 2 * t);
                    mma_bf16(o[g * 2 + t], apl, vh4 + 2 * t);
                    mma_bf16(o[g * 2 + t], aph, vl4 + 2 * t);
                }
            }
        }
    }

    // epilogue: row sums, normalize, write split outproj-A planes
    ls0 += __shfl_xor_sync(0xffffffffu, ls0, 1);
    ls0 += __shfl_xor_sync(0xffffffffu, ls0, 2);
    ls1 += __shfl_xor_sync(0xffffffffu, ls1, 1);
    ls1 += __shfl_xor_sync(0xffffffffu, ls1, 2);
    const float i0 = 1.0f / ls0, i1 = 1.0f / ls1;
    const int row = n * K_ + qt * 128 + r0;
#pragma unroll
    for (int dn = 0; dn < 8; dn++) {
        const int dp = h * 32 + dn * 4 + tig;
        uint32_t hh, ll;
        bsplit(o[dn][0] * i0, o[dn][1] * i0, hh, ll);
        g_yah[row][dp] = hh;  g_yal[row][dp] = ll;
        bsplit(o[dn][2] * i1, o[dn][3] * i1, hh, ll);
        g_yah[row + 8][dp] = hh;  g_yal[row + 8][dp] = ll;
    }
}

// ---------------- launch ----------------
extern "C" void kernel_launch(void* const* d_in, const int* in_sizes, int n_in,
                              void* d_out, int out_size)
{
    const float* query = (const float*)d_in[0];
    const float* key   = (const float*)d_in[1];
    const float* value = (const float*)d_in[2];
    const int*   mask  = (const int*)d_in[3];
    const float* Wq = (const float*)d_in[4];
    const float* bq = (const float*)d_in[5];
    const float* Wk = (const float*)d_in[6];
    const float* bk = (const float*)d_in[7];
    const float* Wv = (const float*)d_in[8];
    const float* bv = (const float*)d_in[9];
    const float* Wp = (const float*)d_in[10];
    const float* bp = (const float*)d_in[11];
    float* out = (float*)d_out;

    cudaFuncSetAttribute(flash_mma, cudaFuncAttributeMaxDynamicSharedMemorySize, FLASH_SMEM);

    mask_pack<<<(N_ * K_ * K_) / 256, 256>>>(mask);
    split_w<<<dim3(512, 4), 256>>>(Wq, Wk, Wv, Wp);
    gemm_mma<<<dim3(32, 8, 3), 256>>>(0, query, key, value, bq, bk, bv, bp, nullptr);
    repack_v<<<dim3(32, 32), 256>>>();
    flash_mma<<<dim3(16, 32), 256, FLASH_SMEM>>>();
    gemm_mma<<<dim3(32, 8, 1), 256>>>(1, nullptr, nullptr, nullptr, bq, bk, bv, bp, out);
}

// round 15
// speedup vs baseline: 1.1228x; 1.1228x over previous
#include <cuda_runtime.h>
#include <cstdint>
#include <float.h>

#define N_   2
#define K_   2048
#define DIN_ 1024
#define H_   16
#define D_   64
#define HD_  1024
#define QSCALE 0.18033688011112043f   // 0.125 * log2(e)

// ---------------- device scratch: separated hi/lo planes ----------------
__device__ __align__(16) uint32_t g_wbh[4][512][1024];  // weights hi (B)
__device__ __align__(16) uint32_t g_wbl[4][512][1024];  // weights lo
__device__ __align__(16) uint32_t g_qph[32][2048][32];  // q hi (scaled), d-pair packed
__device__ __align__(16) uint32_t g_qpl[32][2048][32];
__device__ __align__(16) uint32_t g_kph[32][2048][32];  // k hi
__device__ __align__(16) uint32_t g_kpl[32][2048][32];
__device__ __align__(16) uint32_t g_vh[32][64][1024];   // v hi [nh][d][jpair]
__device__ __align__(16) uint32_t g_vl[32][64][1024];
__device__ __align__(16) float    g_v [32][2048][64];   // v fp32 (for repack)
__device__ __align__(16) uint32_t g_yah[4096][512];     // attn out hi (outproj A)
__device__ __align__(16) uint32_t g_yal[4096][512];
__device__ uint32_t g_mb[(size_t)N_ * K_ * 64];         // packed mask bits

// ---------------- helpers ----------------
__device__ __forceinline__ void bsplit(float x0, float x1, uint32_t& h, uint32_t& l) {
    const uint32_t u0 = __float_as_uint(x0), u1 = __float_as_uint(x1);
    h = __byte_perm(u0, u1, 0x7632);
    const float r0 = x0 - __uint_as_float(u0 & 0xffff0000u);
    const float r1 = x1 - __uint_as_float(u1 & 0xffff0000u);
    asm("cvt.rn.bf16x2.f32 %0, %1, %2;" : "=r"(l) : "f"(r1), "f"(r0));
}
__device__ __forceinline__ void mma_bf16(float* c, const uint32_t* a, const uint32_t* b) {
    asm volatile(
        "mma.sync.aligned.m16n8k16.row.col.f32.bf16.bf16.f32 "
        "{%0,%1,%2,%3}, {%4,%5,%6,%7}, {%8,%9}, {%0,%1,%2,%3};"
        : "+f"(c[0]), "+f"(c[1]), "+f"(c[2]), "+f"(c[3])
        : "r"(a[0]), "r"(a[1]), "r"(a[2]), "r"(a[3]), "r"(b[0]), "r"(b[1]));
}
__device__ __forceinline__ void ldm4(uint32_t* r, uint32_t addr) {
    asm volatile("ldmatrix.sync.aligned.m8n8.x4.shared.b16 {%0,%1,%2,%3}, [%4];"
                 : "=r"(r[0]), "=r"(r[1]), "=r"(r[2]), "=r"(r[3]) : "r"(addr));
}
__device__ __forceinline__ uint32_t smem_u32(const void* p) {
    uint32_t a;
    asm("{ .reg .u64 t; cvta.to.shared.u64 t, %1; cvt.u32.u64 %0, t; }" : "=r"(a) : "l"(p));
    return a;
}
__device__ __forceinline__ float ex2f(float x) {
    float r; asm("ex2.approx.f32 %0, %1;" : "=f"(r) : "f"(x)); return r;
}
__device__ __forceinline__ void cpa(uint32_t dst, const void* src) {
    asm volatile("cp.async.cg.shared.global [%0], [%1], 16;" :: "r"(dst), "l"(src));
}
#define CP_COMMIT() asm volatile("cp.async.commit_group;" ::: "memory")
#define CP_WAIT0()  asm volatile("cp.async.wait_group 0;" ::: "memory")

// ---------------- prep kernels ----------------
__global__ __launch_bounds__(256) void mask_pack(const int* __restrict__ mask) {
    const int idx = blockIdx.x * 256 + threadIdx.x;
    const uint32_t b = __ballot_sync(0xffffffffu, mask[idx] != 0);
    if ((threadIdx.x & 31) == 0) g_mb[idx >> 5] = b;
}

__global__ __launch_bounds__(256) void split_w(const float* __restrict__ wq,
    const float* __restrict__ wk, const float* __restrict__ wv, const float* __restrict__ wp) {
    const int z = blockIdx.y, kp = blockIdx.x, ng = threadIdx.x * 4;
    float4 r0, r1;
    if (z < 3) {
        const float* s = (z == 0) ? wq : (z == 1) ? wk : wv;
        const size_t a0 = (size_t)(ng >> 6) * (DIN_ * D_) + (size_t)(2 * kp) * D_ + (ng & 63);
        r0 = *(const float4*)(s + a0);
        r1 = *(const float4*)(s + a0 + D_);
    } else {
        const size_t a0 = (size_t)(2 * kp) * DIN_ + ng;
        r0 = *(const float4*)(wp + a0);
        r1 = *(const float4*)(wp + a0 + DIN_);
    }
    uint32_t h[4], l[4];
    bsplit(r0.x, r1.x, h[0], l[0]);
    bsplit(r0.y, r1.y, h[1], l[1]);
    bsplit(r0.z, r1.z, h[2], l[2]);
    bsplit(r0.w, r1.w, h[3], l[3]);
    *(uint4*)&g_wbh[z][kp][ng] = make_uint4(h[0], h[1], h[2], h[3]);
    *(uint4*)&g_wbl[z][kp][ng] = make_uint4(l[0], l[1], l[2], l[3]);
}

__global__ __launch_bounds__(256) void repack_v() {
    __shared__ float t[64][68];
    const int nh = blockIdx.y, jt = blockIdx.x, tid = threadIdx.x;
#pragma unroll
    for (int i = 0; i < 4; i++) {
        const int flat = tid + i * 256, tok = flat & 63, d4 = (flat >> 6) * 4;
        *(float4*)&t[tok][d4] = *(const float4*)&g_v[nh][jt * 64 + tok][d4];
    }
    __syncthreads();
    const int jp = tid & 31, dg = tid >> 5;
#pragma unroll
    for (int i = 0; i < 8; i++) {
        const int d = dg * 8 + i;
        uint32_t hh, ll;
        bsplit(t[2 * jp][d], t[2 * jp + 1][d], hh, ll);
        g_vh[nh][d][jt * 32 + jp] = hh;
        g_vl[nh][d][jt * 32 + jp] = ll;
    }
}

// ---------------- GEMM: R9 structure (k16, 2-buf, LDG+STS), templated mode ----------------
// smem words: A [buf][hl][128][12] = 6144, B [buf][hl][8 kp][136] = 4352 -> 42KB static
// MODE 0: grid (32,8,3)  A = fp32 query/key/value (inline bsplit), B = g_wb[z]
//         out: z0 -> g_qp planes (scaled), z1 -> g_kp planes, z2 -> g_v fp32
// MODE 1: grid (32,8,1)  A = g_yah/g_yal planes, B = g_wb[3], out fp32
#define AW(b,hl) (((b)*2+(hl))*1536)
#define BW(b,hl) (6144 + ((b)*2+(hl))*1088)

template<int MODE>
__global__ __launch_bounds__(256, 2) void gemm_mma(
    const float* __restrict__ xq, const float* __restrict__ xk, const float* __restrict__ xv,
    const float* __restrict__ bq, const float* __restrict__ bk,
    const float* __restrict__ bv, const float* __restrict__ bp,
    float* __restrict__ outp)
{
    __shared__ uint32_t gsm[10496];
    const uint32_t sb = smem_u32(gsm);

    const int tid = threadIdx.x, wid = tid >> 5, lane = tid & 31;
    const int gid = lane >> 2, tig = lane & 3, wm = wid >> 2, wn = wid & 3;
    const int m0 = blockIdx.x * 128, by = blockIdx.y;
    const int z = (MODE == 0) ? blockIdx.z : 3;

    const float* Xf = (z == 0) ? xq : (z == 1) ? xk : xv;
    const uint32_t* Bh = &g_wbh[z][0][0];
    const uint32_t* Bl = &g_wbl[z][0][0];
    const float* bias = (z == 0) ? bq : (z == 1) ? bk : (z == 2) ? bv : bp;

    // loader mappings
    const int ar = tid >> 1, t1 = tid & 1;            // A: row, half (kp 4t1..4t1+3)
    const int bkk = tid >> 5, bn4 = (tid & 31) << 2;  // B: kp row, 4-word n group
    const int bcol = by * 128 + bn4;

    float acc[4][4][4] = {};
    uint32_t h4[4], l4[4];   // A chunk staging (hi/lo kpairs)
    uint4 bh4, bl4;

    // ---- load chunk 0 into staging regs ----
    if constexpr (MODE == 0) {
        float4 a0 = *(const float4*)(Xf + (size_t)(m0 + ar) * DIN_ + t1 * 8);
        float4 a1 = *(const float4*)(Xf + (size_t)(m0 + ar) * DIN_ + t1 * 8 + 4);
        bsplit(a0.x, a0.y, h4[0], l4[0]);
        bsplit(a0.z, a0.w, h4[1], l4[1]);
        bsplit(a1.x, a1.y, h4[2], l4[2]);
        bsplit(a1.z, a1.w, h4[3], l4[3]);
    } else {
        uint4 p0 = *(const uint4*)&g_yah[m0 + ar][t1 * 4];
        uint4 p1 = *(const uint4*)&g_yal[m0 + ar][t1 * 4];
        h4[0] = p0.x; h4[1] = p0.y; h4[2] = p0.z; h4[3] = p0.w;
        l4[0] = p1.x; l4[1] = p1.y; l4[2] = p1.z; l4[3] = p1.w;
    }
    bh4 = *(const uint4*)&Bh[(size_t)bkk * 1024 + bcol];
    bl4 = *(const uint4*)&Bl[(size_t)bkk * 1024 + bcol];

    *(uint4*)&gsm[AW(0,0) + ar * 12 + t1 * 4] = make_uint4(h4[0], h4[1], h4[2], h4[3]);
    *(uint4*)&gsm[AW(0,1) + ar * 12 + t1 * 4] = make_uint4(l4[0], l4[1], l4[2], l4[3]);
    *(uint4*)&gsm[BW(0,0) + bkk * 136 + bn4] = bh4;
    *(uint4*)&gsm[BW(0,1) + bkk * 136 + bn4] = bl4;
    __syncthreads();

    for (int c = 0; c < 64; c++) {
        const int buf = c & 1;

        // prefetch chunk c+1 (convert immediately; latency hidden under MMAs)
        if (c < 63) {
            const int kp0 = (c + 1) * 8;
            if constexpr (MODE == 0) {
                float4 a0 = *(const float4*)(Xf + (size_t)(m0 + ar) * DIN_ + kp0 * 2 + t1 * 8);
                float4 a1 = *(const float4*)(Xf + (size_t)(m0 + ar) * DIN_ + kp0 * 2 + t1 * 8 + 4);
                bsplit(a0.x, a0.y, h4[0], l4[0]);
                bsplit(a0.z, a0.w, h4[1], l4[1]);
                bsplit(a1.x, a1.y, h4[2], l4[2]);
                bsplit(a1.z, a1.w, h4[3], l4[3]);
            } else {
                uint4 p0 = *(const uint4*)&g_yah[m0 + ar][kp0 + t1 * 4];
                uint4 p1 = *(const uint4*)&g_yal[m0 + ar][kp0 + t1 * 4];
                h4[0] = p0.x; h4[1] = p0.y; h4[2] = p0.z; h4[3] = p0.w;
                l4[0] = p1.x; l4[1] = p1.y; l4[2] = p1.z; l4[3] = p1.w;
            }
            bh4 = *(const uint4*)&Bh[(size_t)(kp0 + bkk) * 1024 + bcol];
            bl4 = *(const uint4*)&Bl[(size_t)(kp0 + bkk) * 1024 + bcol];
        }

        // ---- one k16 mma step ----
        uint32_t ah[4][4], al[4][4];
#pragma unroll
        for (int mt = 0; mt < 4; mt++) {
            const uint32_t off = (wm * 64 + mt * 16 + (lane & 15)) * 12 + (lane >> 4) * 4;
            ldm4(ah[mt], sb + (AW(buf,0) + off) * 4);
            ldm4(al[mt], sb + (AW(buf,1) + off) * 4);
        }
        uint32_t bh[4][2], bl[4][2];
#pragma unroll
        for (int nt = 0; nt < 4; nt++) {
            const int nc = wn * 32 + nt * 8 + gid;
            bh[nt][0] = gsm[BW(buf,0) + tig * 136 + nc];
            bh[nt][1] = gsm[BW(buf,0) + (tig + 4) * 136 + nc];
            bl[nt][0] = gsm[BW(buf,1) + tig * 136 + nc];
            bl[nt][1] = gsm[BW(buf,1) + (tig + 4) * 136 + nc];
        }
#pragma unroll
        for (int mt = 0; mt < 4; mt++)
#pragma unroll
            for (int nt = 0; nt < 4; nt++) {
                mma_bf16(acc[mt][nt], ah[mt], bh[nt]);
                mma_bf16(acc[mt][nt], al[mt], bh[nt]);
                mma_bf16(acc[mt][nt], ah[mt], bl[nt]);
            }

        // ---- store prefetched chunk into other buffer ----
        if (c < 63) {
            const int nb = buf ^ 1;
            *(uint4*)&gsm[AW(nb,0) + ar * 12 + t1 * 4] = make_uint4(h4[0], h4[1], h4[2], h4[3]);
            *(uint4*)&gsm[AW(nb,1) + ar * 12 + t1 * 4] = make_uint4(l4[0], l4[1], l4[2], l4[3]);
            *(uint4*)&gsm[BW(nb,0) + bkk * 136 + bn4] = bh4;
            *(uint4*)&gsm[BW(nb,1) + bkk * 136 + bn4] = bl4;
            __syncthreads();
        }
    }

    // ---- epilogue ----
#pragma unroll
    for (int mt = 0; mt < 4; mt++)
#pragma unroll
        for (int nt = 0; nt < 4; nt++) {
            const int ng = by * 128 + wn * 32 + nt * 8 + 2 * tig;
            const float b0 = bias[ng], b1 = bias[ng + 1];
#pragma unroll
            for (int half = 0; half < 2; half++) {
                const int m = m0 + wm * 64 + mt * 16 + gid + half * 8;
                float v0 = acc[mt][nt][half * 2 + 0] + b0;
                float v1 = acc[mt][nt][half * 2 + 1] + b1;
                if constexpr (MODE == 1) {
                    *(float2*)(outp + (size_t)m * HD_ + ng) = make_float2(v0, v1);
                } else {
                    const int nn = m >> 11, kk = m & 2047, h = ng >> 6;
                    if (z == 2) {
                        *(float2*)&g_v[nn * 16 + h][kk][ng & 63] = make_float2(v0, v1);
                    } else {
                        if (z == 0) { v0 *= QSCALE; v1 *= QSCALE; }
                        uint32_t hh, ll;
                        bsplit(v0, v1, hh, ll);
                        const int dp = (ng >> 1) & 31;
                        if (z == 0) { g_qph[nn * 16 + h][kk][dp] = hh; g_qpl[nn * 16 + h][kk][dp] = ll; }
                        else        { g_kph[nn * 16 + h][kk][dp] = hh; g_kpl[nn * 16 + h][kk][dp] = ll; }
                    }
                }
            }
        }
}

// ---------------- flash attention: cp.async 2-buf pipeline (R13, unchanged) ----------------
// per-buf words: Kh[64][36]=2304, Kl 2304, Vh[64][36]=2304, Vl 2304 -> 9216
#define FBUF 9216
#define FLASH_SMEM (2 * FBUF * 4)

__global__ __launch_bounds__(256, 2) void flash_mma()
{
    extern __shared__ uint32_t sm[];
    const uint32_t sb = smem_u32(sm);

    const int qt = blockIdx.x, nh = blockIdx.y, n = nh >> 4, h = nh & 15;
    const int tid = threadIdx.x, w = tid >> 5, lane = tid & 31;
    const int gid = lane >> 2, tig = lane & 3, r0 = w * 16 + gid;

    // ---- stage Q planes (cp.async into buf0: Qh@0, Ql@4608) ----
    {
        const int qr = tid >> 1, qc = (tid & 1) * 16;
        const uint32_t dq = sb + (qr * 36 + qc) * 4;
#pragma unroll
        for (int i = 0; i < 4; i++) {
            cpa(dq + i * 16,            &g_qph[nh][qt * 128 + qr][qc + i * 4]);
            cpa(dq + 4608 * 4 + i * 16, &g_qpl[nh][qt * 128 + qr][qc + i * 4]);
        }
        CP_COMMIT();
    }
    CP_WAIT0();
    __syncthreads();

    uint32_t afh[4][4], afl[4][4];
    {
        const uint32_t off = (uint32_t)(w * 16 + (lane & 15)) * 36 + (lane >> 4) * 4;
#pragma unroll
        for (int sp = 0; sp < 4; sp++) {
            ldm4(afh[sp], sb + (off + sp * 8) * 4);
            ldm4(afl[sp], sb + (4608 + off + sp * 8) * 4);
        }
    }
    __syncthreads();   // all warps done reading Q staging before tile0 overwrite

    // cp.async tile loader mapping
    const int fj = tid >> 2, fq = (tid & 3) * 8;
    const uint32_t dK = sb + (fj * 36 + fq) * 4;
    const uint32_t dV = sb + (4608 + fj * 36 + fq) * 4;

#define FCP(kt, buf) do { \
    cpa(dK + (buf) * FBUF * 4,               &g_kph[nh][(kt) * 64 + fj][fq]); \
    cpa(dK + (buf) * FBUF * 4 + 16,          &g_kph[nh][(kt) * 64 + fj][fq + 4]); \
    cpa(dK + ((buf) * FBUF + 2304) * 4,      &g_kpl[nh][(kt) * 64 + fj][fq]); \
    cpa(dK + ((buf) * FBUF + 2304) * 4 + 16, &g_kpl[nh][(kt) * 64 + fj][fq + 4]); \
    cpa(dV + (buf) * FBUF * 4,               &g_vh[nh][fj][(kt) * 32 + fq]); \
    cpa(dV + (buf) * FBUF * 4 + 16,          &g_vh[nh][fj][(kt) * 32 + fq + 4]); \
    cpa(dV + ((buf) * FBUF + 2304) * 4,      &g_vl[nh][fj][(kt) * 32 + fq]); \
    cpa(dV + ((buf) * FBUF + 2304) * 4 + 16, &g_vl[nh][fj][(kt) * 32 + fq + 4]); \
    CP_COMMIT(); } while (0)

    FCP(0, 0);

    float o[8][4] = {};
    float ls0 = 0.f, ls1 = 0.f;
    const uint32_t* mr0 = g_mb + (size_t)(n * K_ + qt * 128 + r0) * 64;
    const uint32_t* mr1 = mr0 + 8 * 64;

    const uint32_t brow = (lane & 7) + ((lane & 16) ? 8u : 0u);
    const uint32_t bbyt = (lane & 8) ? 16u : 0u;

#pragma unroll 2
    for (int kt = 0; kt < 32; kt++) {
        const int buf = kt & 1;
        // mask prefetch first: LDG latency hides under QK MMAs
        const uint2 w0 = *(const uint2*)(mr0 + kt * 2);
        const uint2 w1 = *(const uint2*)(mr1 + kt * 2);
        CP_WAIT0();
        __syncthreads();
        if (kt + 1 < 32) { FCP(kt + 1, buf ^ 1); } else { CP_COMMIT(); }

        // S = Q K^T (3-term)
        float s[8][4] = {};
#pragma unroll
        for (int sp = 0; sp < 4; sp++) {
#pragma unroll
            for (int g = 0; g < 4; g++) {
                const uint32_t base = (buf * FBUF + (g * 16 + brow) * 36 + sp * 8) * 4 + bbyt;
                uint32_t kh4[4], kl4[4];
                ldm4(kh4, sb + base);
                ldm4(kl4, sb + 2304 * 4 + base);
#pragma unroll
                for (int t = 0; t < 2; t++) {
                    mma_bf16(s[g * 2 + t], afh[sp], kh4 + 2 * t);
                    mma_bf16(s[g * 2 + t], afl[sp], kh4 + 2 * t);
                    mma_bf16(s[g * 2 + t], afh[sp], kl4 + 2 * t);
                }
            }
        }

        // mask + exp2 (no-max softmax; scale folded into q)
#pragma unroll
        for (int nt = 0; nt < 8; nt++) {
            const int jb = nt * 8 + 2 * tig;
#pragma unroll
            for (int cc = 0; cc < 4; cc++) {
                const int j = jb + (cc & 1);
                const uint32_t word = (cc < 2) ? ((j < 32) ? w0.x : w0.y)
                                               : ((j < 32) ? w1.x : w1.y);
                s[nt][cc] = ((word >> (j & 31)) & 1u) ? 0.f : ex2f(s[nt][cc]);
            }
            ls0 += s[nt][0] + s[nt][1];
            ls1 += s[nt][2] + s[nt][3];
        }

        // O += P V (P frags in registers)
#pragma unroll
        for (int sp = 0; sp < 4; sp++) {
            uint32_t aph[4], apl[4];
            bsplit(s[2 * sp][0],     s[2 * sp][1],     aph[0], apl[0]);
            bsplit(s[2 * sp][2],     s[2 * sp][3],     aph[1], apl[1]);
            bsplit(s[2 * sp + 1][0], s[2 * sp + 1][1], aph[2], apl[2]);
            bsplit(s[2 * sp + 1][2], s[2 * sp + 1][3], aph[3], apl[3]);
#pragma unroll
            for (int g = 0; g < 4; g++) {
                const uint32_t base = (buf * FBUF + 4608 + (g * 16 + brow) * 36 + sp * 8) * 4 + bbyt;
                uint32_t vh4[4], vl4[4];
                ldm4(vh4, sb + base);
                ldm4(vl4, sb + 2304 * 4 + base);
#pragma unroll
                for (int t = 0; t < 2; t++) {
                    mma_bf16(o[g * 2 + t], aph, vh4 + 2 * t);
                    mma_bf16(o[g * 2 + t], apl, vh4 + 2 * t);
                    mma_bf16(o[g * 2 + t], aph, vl4 + 2 * t);
                }
            }
        }
    }

    // epilogue: row sums, normalize, write split outproj-A planes
    ls0 += __shfl_xor_sync(0xffffffffu, ls0, 1);
    ls0 += __shfl_xor_sync(0xffffffffu, ls0, 2);
    ls1 += __shfl_xor_sync(0xffffffffu, ls1, 1);
    ls1 += __shfl_xor_sync(0xffffffffu, ls1, 2);
    const float i0 = 1.0f / ls0, i1 = 1.0f / ls1;
    const int row = n * K_ + qt * 128 + r0;
#pragma unroll
    for (int dn = 0; dn < 8; dn++) {
        const int dp = h * 32 + dn * 4 + tig;
        uint32_t hh, ll;
        bsplit(o[dn][0] * i0, o[dn][1] * i0, hh, ll);
        g_yah[row][dp] = hh;  g_yal[row][dp] = ll;
        bsplit(o[dn][2] * i1, o[dn][3] * i1, hh, ll);
        g_yah[row + 8][dp] = hh;  g_yal[row + 8][dp] = ll;
    }
}

// ---------------- launch ----------------
extern "C" void kernel_launch(void* const* d_in, const int* in_sizes, int n_in,
                              void* d_out, int out_size)
{
    const float* query = (const float*)d_in[0];
    const float* key   = (const float*)d_in[1];
    const float* value = (const float*)d_in[2];
    const int*   mask  = (const int*)d_in[3];
    const float* Wq = (const float*)d_in[4];
    const float* bq = (const float*)d_in[5];
    const float* Wk = (const float*)d_in[6];
    const float* bk = (const float*)d_in[7];
    const float* Wv = (const float*)d_in[8];
    const float* bv = (const float*)d_in[9];
    const float* Wp = (const float*)d_in[10];
    const float* bp = (const float*)d_in[11];
    float* out = (float*)d_out;

    cudaFuncSetAttribute(flash_mma, cudaFuncAttributeMaxDynamicSharedMemorySize, FLASH_SMEM);

    mask_pack<<<(N_ * K_ * K_) / 256, 256>>>(mask);
    split_w<<<dim3(512, 4), 256>>>(Wq, Wk, Wv, Wp);
    gemm_mma<0><<<dim3(32, 8, 3), 256>>>(query, key, value, bq, bk, bv, bp, nullptr);
    repack_v<<<dim3(32, 32), 256>>>();
    flash_mma<<<dim3(16, 32), 256, FLASH_SMEM>>>();
    gemm_mma<1><<<dim3(32, 8, 1), 256>>>(nullptr, nullptr, nullptr, bq, bk, bv, bp, out);
}

// round 16
// speedup vs baseline: 1.1288x; 1.0053x over previous
#include <cuda_runtime.h>
#include <cstdint>
#include <float.h>

#define N_   2
#define K_   2048
#define DIN_ 1024
#define H_   16
#define D_   64
#define HD_  1024
#define QSCALE 0.18033688011112043f   // 0.125 * log2(e)

// ---------------- device scratch: separated hi/lo planes ----------------
__device__ __align__(16) uint32_t g_wbh[4][512][1024];  // weights hi (B)
__device__ __align__(16) uint32_t g_wbl[4][512][1024];  // weights lo
__device__ __align__(16) uint32_t g_qph[32][2048][32];  // q hi (scaled), d-pair packed
__device__ __align__(16) uint32_t g_qpl[32][2048][32];
__device__ __align__(16) uint32_t g_kph[32][2048][32];  // k hi
__device__ __align__(16) uint32_t g_kpl[32][2048][32];
__device__ __align__(16) uint32_t g_vh[32][64][1024];   // v hi [nh][d][jpair]
__device__ __align__(16) uint32_t g_vl[32][64][1024];
__device__ __align__(16) float    g_v [32][2048][64];   // v fp32 (for repack)
__device__ __align__(16) uint32_t g_yah[4096][512];     // attn out hi (outproj A)
__device__ __align__(16) uint32_t g_yal[4096][512];
__device__ uint32_t g_mb[(size_t)N_ * K_ * 64];         // packed mask bits

// ---------------- helpers ----------------
__device__ __forceinline__ void bsplit(float x0, float x1, uint32_t& h, uint32_t& l) {
    const uint32_t u0 = __float_as_uint(x0), u1 = __float_as_uint(x1);
    h = __byte_perm(u0, u1, 0x7632);
    const float r0 = x0 - __uint_as_float(u0 & 0xffff0000u);
    const float r1 = x1 - __uint_as_float(u1 & 0xffff0000u);
    asm("cvt.rn.bf16x2.f32 %0, %1, %2;" : "=r"(l) : "f"(r1), "f"(r0));
}
__device__ __forceinline__ void mma_bf16(float* c, const uint32_t* a, const uint32_t* b) {
    asm volatile(
        "mma.sync.aligned.m16n8k16.row.col.f32.bf16.bf16.f32 "
        "{%0,%1,%2,%3}, {%4,%5,%6,%7}, {%8,%9}, {%0,%1,%2,%3};"
        : "+f"(c[0]), "+f"(c[1]), "+f"(c[2]), "+f"(c[3])
        : "r"(a[0]), "r"(a[1]), "r"(a[2]), "r"(a[3]), "r"(b[0]), "r"(b[1]));
}
__device__ __forceinline__ void ldm4(uint32_t* r, uint32_t addr) {
    asm volatile("ldmatrix.sync.aligned.m8n8.x4.shared.b16 {%0,%1,%2,%3}, [%4];"
                 : "=r"(r[0]), "=r"(r[1]), "=r"(r[2]), "=r"(r[3]) : "r"(addr));
}
__device__ __forceinline__ uint32_t smem_u32(const void* p) {
    uint32_t a;
    asm("{ .reg .u64 t; cvta.to.shared.u64 t, %1; cvt.u32.u64 %0, t; }" : "=r"(a) : "l"(p));
    return a;
}
__device__ __forceinline__ float ex2f(float x) {
    float r; asm("ex2.approx.f32 %0, %1;" : "=f"(r) : "f"(x)); return r;
}
__device__ __forceinline__ void cpa(uint32_t dst, const void* src) {
    asm volatile("cp.async.cg.shared.global [%0], [%1], 16;" :: "r"(dst), "l"(src));
}
#define CP_COMMIT() asm volatile("cp.async.commit_group;" ::: "memory")
#define CP_WAIT0()  asm volatile("cp.async.wait_group 0;" ::: "memory")

// ---------------- prep kernels ----------------
__global__ __launch_bounds__(256) void mask_pack(const int* __restrict__ mask) {
    const int idx = blockIdx.x * 256 + threadIdx.x;
    const uint32_t b = __ballot_sync(0xffffffffu, mask[idx] != 0);
    if ((threadIdx.x & 31) == 0) g_mb[idx >> 5] = b;
}

__global__ __launch_bounds__(256) void split_w(const float* __restrict__ wq,
    const float* __restrict__ wk, const float* __restrict__ wv, const float* __restrict__ wp) {
    const int z = blockIdx.y, kp = blockIdx.x, ng = threadIdx.x * 4;
    float4 r0, r1;
    if (z < 3) {
        const float* s = (z == 0) ? wq : (z == 1) ? wk : wv;
        const size_t a0 = (size_t)(ng >> 6) * (DIN_ * D_) + (size_t)(2 * kp) * D_ + (ng & 63);
        r0 = *(const float4*)(s + a0);
        r1 = *(const float4*)(s + a0 + D_);
    } else {
        const size_t a0 = (size_t)(2 * kp) * DIN_ + ng;
        r0 = *(const float4*)(wp + a0);
        r1 = *(const float4*)(wp + a0 + DIN_);
    }
    uint32_t h[4], l[4];
    bsplit(r0.x, r1.x, h[0], l[0]);
    bsplit(r0.y, r1.y, h[1], l[1]);
    bsplit(r0.z, r1.z, h[2], l[2]);
    bsplit(r0.w, r1.w, h[3], l[3]);
    *(uint4*)&g_wbh[z][kp][ng] = make_uint4(h[0], h[1], h[2], h[3]);
    *(uint4*)&g_wbl[z][kp][ng] = make_uint4(l[0], l[1], l[2], l[3]);
}

__global__ __launch_bounds__(256) void repack_v() {
    __shared__ float t[64][68];
    const int nh = blockIdx.y, jt = blockIdx.x, tid = threadIdx.x;
#pragma unroll
    for (int i = 0; i < 4; i++) {
        const int flat = tid + i * 256, tok = flat & 63, d4 = (flat >> 6) * 4;
        *(float4*)&t[tok][d4] = *(const float4*)&g_v[nh][jt * 64 + tok][d4];
    }
    __syncthreads();
    const int jp = tid & 31, dg = tid >> 5;
#pragma unroll
    for (int i = 0; i < 8; i++) {
        const int d = dg * 8 + i;
        uint32_t hh, ll;
        bsplit(t[2 * jp][d], t[2 * jp + 1][d], hh, ll);
        g_vh[nh][d][jt * 32 + jp] = hh;
        g_vl[nh][d][jt * 32 + jp] = ll;
    }
}

// ---------------- GEMM: k16, 2-buf, LDG+STS, templated mode, term-major MMA ----------------
#define AW(b,hl) (((b)*2+(hl))*1536)
#define BW(b,hl) (6144 + ((b)*2+(hl))*1088)

template<int MODE>
__global__ __launch_bounds__(256, 2) void gemm_mma(
    const float* __restrict__ xq, const float* __restrict__ xk, const float* __restrict__ xv,
    const float* __restrict__ bq, const float* __restrict__ bk,
    const float* __restrict__ bv, const float* __restrict__ bp,
    float* __restrict__ outp)
{
    __shared__ uint32_t gsm[10496];
    const uint32_t sb = smem_u32(gsm);

    const int tid = threadIdx.x, wid = tid >> 5, lane = tid & 31;
    const int gid = lane >> 2, tig = lane & 3, wm = wid >> 2, wn = wid & 3;
    const int m0 = blockIdx.x * 128, by = blockIdx.y;
    const int z = (MODE == 0) ? blockIdx.z : 3;

    const float* Xf = (z == 0) ? xq : (z == 1) ? xk : xv;
    const uint32_t* Bh = &g_wbh[z][0][0];
    const uint32_t* Bl = &g_wbl[z][0][0];
    const float* bias = (z == 0) ? bq : (z == 1) ? bk : (z == 2) ? bv : bp;

    const int ar = tid >> 1, t1 = tid & 1;
    const int bkk = tid >> 5, bn4 = (tid & 31) << 2;
    const int bcol = by * 128 + bn4;

    float acc[4][4][4] = {};
    uint32_t h4[4], l4[4];
    uint4 bh4, bl4;

    if constexpr (MODE == 0) {
        float4 a0 = *(const float4*)(Xf + (size_t)(m0 + ar) * DIN_ + t1 * 8);
        float4 a1 = *(const float4*)(Xf + (size_t)(m0 + ar) * DIN_ + t1 * 8 + 4);
        bsplit(a0.x, a0.y, h4[0], l4[0]);
        bsplit(a0.z, a0.w, h4[1], l4[1]);
        bsplit(a1.x, a1.y, h4[2], l4[2]);
        bsplit(a1.z, a1.w, h4[3], l4[3]);
    } else {
        uint4 p0 = *(const uint4*)&g_yah[m0 + ar][t1 * 4];
        uint4 p1 = *(const uint4*)&g_yal[m0 + ar][t1 * 4];
        h4[0] = p0.x; h4[1] = p0.y; h4[2] = p0.z; h4[3] = p0.w;
        l4[0] = p1.x; l4[1] = p1.y; l4[2] = p1.z; l4[3] = p1.w;
    }
    bh4 = *(const uint4*)&Bh[(size_t)bkk * 1024 + bcol];
    bl4 = *(const uint4*)&Bl[(size_t)bkk * 1024 + bcol];

    *(uint4*)&gsm[AW(0,0) + ar * 12 + t1 * 4] = make_uint4(h4[0], h4[1], h4[2], h4[3]);
    *(uint4*)&gsm[AW(0,1) + ar * 12 + t1 * 4] = make_uint4(l4[0], l4[1], l4[2], l4[3]);
    *(uint4*)&gsm[BW(0,0) + bkk * 136 + bn4] = bh4;
    *(uint4*)&gsm[BW(0,1) + bkk * 136 + bn4] = bl4;
    __syncthreads();

    for (int c = 0; c < 64; c++) {
        const int buf = c & 1;

        if (c < 63) {
            const int kp0 = (c + 1) * 8;
            if constexpr (MODE == 0) {
                float4 a0 = *(const float4*)(Xf + (size_t)(m0 + ar) * DIN_ + kp0 * 2 + t1 * 8);
                float4 a1 = *(const float4*)(Xf + (size_t)(m0 + ar) * DIN_ + kp0 * 2 + t1 * 8 + 4);
                bsplit(a0.x, a0.y, h4[0], l4[0]);
                bsplit(a0.z, a0.w, h4[1], l4[1]);
                bsplit(a1.x, a1.y, h4[2], l4[2]);
                bsplit(a1.z, a1.w, h4[3], l4[3]);
            } else {
                uint4 p0 = *(const uint4*)&g_yah[m0 + ar][kp0 + t1 * 4];
                uint4 p1 = *(const uint4*)&g_yal[m0 + ar][kp0 + t1 * 4];
                h4[0] = p0.x; h4[1] = p0.y; h4[2] = p0.z; h4[3] = p0.w;
                l4[0] = p1.x; l4[1] = p1.y; l4[2] = p1.z; l4[3] = p1.w;
            }
            bh4 = *(const uint4*)&Bh[(size_t)(kp0 + bkk) * 1024 + bcol];
            bl4 = *(const uint4*)&Bl[(size_t)(kp0 + bkk) * 1024 + bcol];
        }

        uint32_t ah[4][4], al[4][4];
#pragma unroll
        for (int mt = 0; mt < 4; mt++) {
            const uint32_t off = (wm * 64 + mt * 16 + (lane & 15)) * 12 + (lane >> 4) * 4;
            ldm4(ah[mt], sb + (AW(buf,0) + off) * 4);
            ldm4(al[mt], sb + (AW(buf,1) + off) * 4);
        }
        uint32_t bhf[4][2], blf[4][2];
#pragma unroll
        for (int nt = 0; nt < 4; nt++) {
            const int nc = wn * 32 + nt * 8 + gid;
            bhf[nt][0] = gsm[BW(buf,0) + tig * 136 + nc];
            bhf[nt][1] = gsm[BW(buf,0) + (tig + 4) * 136 + nc];
            blf[nt][0] = gsm[BW(buf,1) + tig * 136 + nc];
            blf[nt][1] = gsm[BW(buf,1) + (tig + 4) * 136 + nc];
        }
        // term-major: same-accumulator reuse distance = 16 (no RAW stall on tensor pipe)
#pragma unroll
        for (int mt = 0; mt < 4; mt++)
#pragma unroll
            for (int nt = 0; nt < 4; nt++)
                mma_bf16(acc[mt][nt], ah[mt], bhf[nt]);
#pragma unroll
        for (int mt = 0; mt < 4; mt++)
#pragma unroll
            for (int nt = 0; nt < 4; nt++)
                mma_bf16(acc[mt][nt], al[mt], bhf[nt]);
#pragma unroll
        for (int mt = 0; mt < 4; mt++)
#pragma unroll
            for (int nt = 0; nt < 4; nt++)
                mma_bf16(acc[mt][nt], ah[mt], blf[nt]);

        if (c < 63) {
            const int nb = buf ^ 1;
            *(uint4*)&gsm[AW(nb,0) + ar * 12 + t1 * 4] = make_uint4(h4[0], h4[1], h4[2], h4[3]);
            *(uint4*)&gsm[AW(nb,1) + ar * 12 + t1 * 4] = make_uint4(l4[0], l4[1], l4[2], l4[3]);
            *(uint4*)&gsm[BW(nb,0) + bkk * 136 + bn4] = bh4;
            *(uint4*)&gsm[BW(nb,1) + bkk * 136 + bn4] = bl4;
            __syncthreads();
        }
    }

    // ---- epilogue ----
#pragma unroll
    for (int mt = 0; mt < 4; mt++)
#pragma unroll
        for (int nt = 0; nt < 4; nt++) {
            const int ng = by * 128 + wn * 32 + nt * 8 + 2 * tig;
            const float b0 = bias[ng], b1 = bias[ng + 1];
#pragma unroll
            for (int half = 0; half < 2; half++) {
                const int m = m0 + wm * 64 + mt * 16 + gid + half * 8;
                float v0 = acc[mt][nt][half * 2 + 0] + b0;
                float v1 = acc[mt][nt][half * 2 + 1] + b1;
                if constexpr (MODE == 1) {
                    *(float2*)(outp + (size_t)m * HD_ + ng) = make_float2(v0, v1);
                } else {
                    const int nn = m >> 11, kk = m & 2047, h = ng >> 6;
                    if (z == 2) {
                        *(float2*)&g_v[nn * 16 + h][kk][ng & 63] = make_float2(v0, v1);
                    } else {
                        if (z == 0) { v0 *= QSCALE; v1 *= QSCALE; }
                        uint32_t hh, ll;
                        bsplit(v0, v1, hh, ll);
                        const int dp = (ng >> 1) & 31;
                        if (z == 0) { g_qph[nn * 16 + h][kk][dp] = hh; g_qpl[nn * 16 + h][kk][dp] = ll; }
                        else        { g_kph[nn * 16 + h][kk][dp] = hh; g_kpl[nn * 16 + h][kk][dp] = ll; }
                    }
                }
            }
        }
}

// ---------------- flash attention: cp.async 2-buf, term-interleaved MMA ----------------
#define FBUF 9216
#define FLASH_SMEM (2 * FBUF * 4)

__global__ __launch_bounds__(256, 2) void flash_mma()
{
    extern __shared__ uint32_t sm[];
    const uint32_t sb = smem_u32(sm);

    const int qt = blockIdx.x, nh = blockIdx.y, n = nh >> 4, h = nh & 15;
    const int tid = threadIdx.x, w = tid >> 5, lane = tid & 31;
    const int gid = lane >> 2, tig = lane & 3, r0 = w * 16 + gid;

    // ---- stage Q planes (cp.async into buf0: Qh@0, Ql@4608) ----
    {
        const int qr = tid >> 1, qc = (tid & 1) * 16;
        const uint32_t dq = sb + (qr * 36 + qc) * 4;
#pragma unroll
        for (int i = 0; i < 4; i++) {
            cpa(dq + i * 16,            &g_qph[nh][qt * 128 + qr][qc + i * 4]);
            cpa(dq + 4608 * 4 + i * 16, &g_qpl[nh][qt * 128 + qr][qc + i * 4]);
        }
        CP_COMMIT();
    }
    CP_WAIT0();
    __syncthreads();

    uint32_t afh[4][4], afl[4][4];
    {
        const uint32_t off = (uint32_t)(w * 16 + (lane & 15)) * 36 + (lane >> 4) * 4;
#pragma unroll
        for (int sp = 0; sp < 4; sp++) {
            ldm4(afh[sp], sb + (off + sp * 8) * 4);
            ldm4(afl[sp], sb + (4608 + off + sp * 8) * 4);
        }
    }
    __syncthreads();

    const int fj = tid >> 2, fq = (tid & 3) * 8;
    const uint32_t dK = sb + (fj * 36 + fq) * 4;
    const uint32_t dV = sb + (4608 + fj * 36 + fq) * 4;

#define FCP(kt, buf) do { \
    cpa(dK + (buf) * FBUF * 4,               &g_kph[nh][(kt) * 64 + fj][fq]); \
    cpa(dK + (buf) * FBUF * 4 + 16,          &g_kph[nh][(kt) * 64 + fj][fq + 4]); \
    cpa(dK + ((buf) * FBUF + 2304) * 4,      &g_kpl[nh][(kt) * 64 + fj][fq]); \
    cpa(dK + ((buf) * FBUF + 2304) * 4 + 16, &g_kpl[nh][(kt) * 64 + fj][fq + 4]); \
    cpa(dV + (buf) * FBUF * 4,               &g_vh[nh][fj][(kt) * 32 + fq]); \
    cpa(dV + (buf) * FBUF * 4 + 16,          &g_vh[nh][fj][(kt) * 32 + fq + 4]); \
    cpa(dV + ((buf) * FBUF + 2304) * 4,      &g_vl[nh][fj][(kt) * 32 + fq]); \
    cpa(dV + ((buf) * FBUF + 2304) * 4 + 16, &g_vl[nh][fj][(kt) * 32 + fq + 4]); \
    CP_COMMIT(); } while (0)

    FCP(0, 0);

    float o[8][4] = {};
    float ls0 = 0.f, ls1 = 0.f;
    const uint32_t* mr0 = g_mb + (size_t)(n * K_ + qt * 128 + r0) * 64;
    const uint32_t* mr1 = mr0 + 8 * 64;

    const uint32_t brow = (lane & 7) + ((lane & 16) ? 8u : 0u);
    const uint32_t bbyt = (lane & 8) ? 16u : 0u;

#pragma unroll 2
    for (int kt = 0; kt < 32; kt++) {
        const int buf = kt & 1;
        const uint2 w0 = *(const uint2*)(mr0 + kt * 2);
        const uint2 w1 = *(const uint2*)(mr1 + kt * 2);
        CP_WAIT0();
        __syncthreads();
        if (kt + 1 < 32) { FCP(kt + 1, buf ^ 1); } else { CP_COMMIT(); }

        // S = Q K^T (3-term, term-interleaved: same-acc distance 2)
        float s[8][4] = {};
#pragma unroll
        for (int sp = 0; sp < 4; sp++) {
#pragma unroll
            for (int g = 0; g < 4; g++) {
                const uint32_t base = (buf * FBUF + (g * 16 + brow) * 36 + sp * 8) * 4 + bbyt;
                uint32_t kh4[4], kl4[4];
                ldm4(kh4, sb + base);
                ldm4(kl4, sb + 2304 * 4 + base);
                mma_bf16(s[g * 2 + 0], afh[sp], kh4);
                mma_bf16(s[g * 2 + 1], afh[sp], kh4 + 2);
                mma_bf16(s[g * 2 + 0], afl[sp], kh4);
                mma_bf16(s[g * 2 + 1], afl[sp], kh4 + 2);
                mma_bf16(s[g * 2 + 0], afh[sp], kl4);
                mma_bf16(s[g * 2 + 1], afh[sp], kl4 + 2);
            }
        }

        // mask + exp2 (no-max softmax)
#pragma unroll
        for (int nt = 0; nt < 8; nt++) {
            const int jb = nt * 8 + 2 * tig;
#pragma unroll
            for (int cc = 0; cc < 4; cc++) {
                const int j = jb + (cc & 1);
                const uint32_t word = (cc < 2) ? ((j < 32) ? w0.x : w0.y)
                                               : ((j < 32) ? w1.x : w1.y);
                s[nt][cc] = ((word >> (j & 31)) & 1u) ? 0.f : ex2f(s[nt][cc]);
            }
            ls0 += s[nt][0] + s[nt][1];
            ls1 += s[nt][2] + s[nt][3];
        }

        // O += P V (term-interleaved)
#pragma unroll
        for (int sp = 0; sp < 4; sp++) {
            uint32_t aph[4], apl[4];
            bsplit(s[2 * sp][0],     s[2 * sp][1],     aph[0], apl[0]);
            bsplit(s[2 * sp][2],     s[2 * sp][3],     aph[1], apl[1]);
            bsplit(s[2 * sp + 1][0], s[2 * sp + 1][1], aph[2], apl[2]);
            bsplit(s[2 * sp + 1][2], s[2 * sp + 1][3], aph[3], apl[3]);
#pragma unroll
            for (int g = 0; g < 4; g++) {
                const uint32_t base = (buf * FBUF + 4608 + (g * 16 + brow) * 36 + sp * 8) * 4 + bbyt;
                uint32_t vh4[4], vl4[4];
                ldm4(vh4, sb + base);
                ldm4(vl4, sb + 2304 * 4 + base);
                mma_bf16(o[g * 2 + 0], aph, vh4);
                mma_bf16(o[g * 2 + 1], aph, vh4 + 2);
                mma_bf16(o[g * 2 + 0], apl, vh4);
                mma_bf16(o[g * 2 + 1], apl, vh4 + 2);
                mma_bf16(o[g * 2 + 0], aph, vl4);
                mma_bf16(o[g * 2 + 1], aph, vl4 + 2);
            }
        }
    }

    // epilogue
    ls0 += __shfl_xor_sync(0xffffffffu, ls0, 1);
    ls0 += __shfl_xor_sync(0xffffffffu, ls0, 2);
    ls1 += __shfl_xor_sync(0xffffffffu, ls1, 1);
    ls1 += __shfl_xor_sync(0xffffffffu, ls1, 2);
    const float i0 = 1.0f / ls0, i1 = 1.0f / ls1;
    const int row = n * K_ + qt * 128 + r0;
#pragma unroll
    for (int dn = 0; dn < 8; dn++) {
        const int dp = h * 32 + dn * 4 + tig;
        uint32_t hh, ll;
        bsplit(o[dn][0] * i0, o[dn][1] * i0, hh, ll);
        g_yah[row][dp] = hh;  g_yal[row][dp] = ll;
        bsplit(o[dn][2] * i1, o[dn][3] * i1, hh, ll);
        g_yah[row + 8][dp] = hh;  g_yal[row + 8][dp] = ll;
    }
}

// ---------------- launch ----------------
extern "C" void kernel_launch(void* const* d_in, const int* in_sizes, int n_in,
                              void* d_out, int out_size)
{
    const float* query = (const float*)d_in[0];
    const float* key   = (const float*)d_in[1];
    const float* value = (const float*)d_in[2];
    const int*   mask  = (const int*)d_in[3];
    const float* Wq = (const float*)d_in[4];
    const float* bq = (const float*)d_in[5];
    const float* Wk = (const float*)d_in[6];
    const float* bk = (const float*)d_in[7];
    const float* Wv = (const float*)d_in[8];
    const float* bv = (const float*)d_in[9];
    const float* Wp = (const float*)d_in[10];
    const float* bp = (const float*)d_in[11];
    float* out = (float*)d_out;

    cudaFuncSetAttribute(flash_mma, cudaFuncAttributeMaxDynamicSharedMemorySize, FLASH_SMEM);

    mask_pack<<<(N_ * K_ * K_) / 256, 256>>>(mask);
    split_w<<<dim3(512, 4), 256>>>(Wq, Wk, Wv, Wp);
    gemm_mma<0><<<dim3(32, 8, 3), 256>>>(query, key, value, bq, bk, bv, bp, nullptr);
    repack_v<<<dim3(32, 32), 256>>>();
    flash_mma<<<dim3(16, 32), 256, FLASH_SMEM>>>();
    gemm_mma<1><<<dim3(32, 8, 1), 256>>>(nullptr, nullptr, nullptr, bq, bk, bv, bp, out);
}

// round 17
// speedup vs baseline: 1.5145x; 1.3417x over previous
#include <cuda_runtime.h>
#include <cuda_fp16.h>
#include <cstdint>
#include <float.h>

#define N_   2
#define K_   2048
#define DIN_ 1024
#define H_   16
#define D_   64
#define HD_  1024
#define QSCALE 0.18033688011112043f   // 0.125 * log2(e)
#define PBIAS  8.0f                   // softmax log2 bias (cancels in normalization)

// ---------------- device scratch ----------------
__device__ __align__(16) uint32_t g_wb16[4][512][1024]; // weights fp16, k-pair packed
__device__ __align__(16) uint32_t g_qph[32][2048][32];  // q hi (scaled) fp16
__device__ __align__(16) uint32_t g_qpl[32][2048][32];  // q lo (residual)
__device__ __align__(16) uint32_t g_kp16[32][2048][32]; // k fp16 single plane
__device__ __align__(16) uint32_t g_v16[32][64][1024];  // v fp16 [nh][d][jpair]
__device__ __align__(16) float    g_v [32][2048][64];   // v fp32 (for repack)
__device__ __align__(16) uint32_t g_yah[4096][512];     // attn out hi (outproj A)
__device__ __align__(16) uint32_t g_yal[4096][512];     // attn out lo
__device__ uint32_t g_mb[(size_t)N_ * K_ * 64];         // packed mask bits

// ---------------- helpers ----------------
// pack (x0 -> low, x1 -> high) as fp16x2, rn
__device__ __forceinline__ uint32_t hpack(float x0, float x1) {
    uint32_t r;
    asm("cvt.rn.f16x2.f32 %0, %1, %2;" : "=r"(r) : "f"(x1), "f"(x0));
    return r;
}
// 2-term fp16 split: x = h + l exactly to ~2^-24
__device__ __forceinline__ void hsplit(float x0, float x1, uint32_t& h, uint32_t& l) {
    h = hpack(x0, x1);
    const __half2 hv = *reinterpret_cast<const __half2*>(&h);
    const float r0 = x0 - __low2float(hv);
    const float r1 = x1 - __high2float(hv);
    l = hpack(r0, r1);
}
__device__ __forceinline__ void mma_fp16(float* c, const uint32_t* a, const uint32_t* b) {
    asm volatile(
        "mma.sync.aligned.m16n8k16.row.col.f32.f16.f16.f32 "
        "{%0,%1,%2,%3}, {%4,%5,%6,%7}, {%8,%9}, {%0,%1,%2,%3};"
        : "+f"(c[0]), "+f"(c[1]), "+f"(c[2]), "+f"(c[3])
        : "r"(a[0]), "r"(a[1]), "r"(a[2]), "r"(a[3]), "r"(b[0]), "r"(b[1]));
}
__device__ __forceinline__ void ldm4(uint32_t* r, uint32_t addr) {
    asm volatile("ldmatrix.sync.aligned.m8n8.x4.shared.b16 {%0,%1,%2,%3}, [%4];"
                 : "=r"(r[0]), "=r"(r[1]), "=r"(r[2]), "=r"(r[3]) : "r"(addr));
}
__device__ __forceinline__ uint32_t smem_u32(const void* p) {
    uint32_t a;
    asm("{ .reg .u64 t; cvta.to.shared.u64 t, %1; cvt.u32.u64 %0, t; }" : "=r"(a) : "l"(p));
    return a;
}
__device__ __forceinline__ float ex2f(float x) {
    float r; asm("ex2.approx.f32 %0, %1;" : "=f"(r) : "f"(x)); return r;
}
__device__ __forceinline__ void cpa(uint32_t dst, const void* src) {
    asm volatile("cp.async.cg.shared.global [%0], [%1], 16;" :: "r"(dst), "l"(src));
}
#define CP_COMMIT() asm volatile("cp.async.commit_group;" ::: "memory")
#define CP_WAIT0()  asm volatile("cp.async.wait_group 0;" ::: "memory")

// ---------------- prep kernels ----------------
__global__ __launch_bounds__(256) void mask_pack(const int* __restrict__ mask) {
    const int idx = blockIdx.x * 256 + threadIdx.x;
    const uint32_t b = __ballot_sync(0xffffffffu, mask[idx] != 0);
    if ((threadIdx.x & 31) == 0) g_mb[idx >> 5] = b;
}

__global__ __launch_bounds__(256) void split_w(const float* __restrict__ wq,
    const float* __restrict__ wk, const float* __restrict__ wv, const float* __restrict__ wp) {
    const int z = blockIdx.y, kp = blockIdx.x, ng = threadIdx.x * 4;
    float4 r0, r1;
    if (z < 3) {
        const float* s = (z == 0) ? wq : (z == 1) ? wk : wv;
        const size_t a0 = (size_t)(ng >> 6) * (DIN_ * D_) + (size_t)(2 * kp) * D_ + (ng & 63);
        r0 = *(const float4*)(s + a0);
        r1 = *(const float4*)(s + a0 + D_);
    } else {
        const size_t a0 = (size_t)(2 * kp) * DIN_ + ng;
        r0 = *(const float4*)(wp + a0);
        r1 = *(const float4*)(wp + a0 + DIN_);
    }
    *(uint4*)&g_wb16[z][kp][ng] = make_uint4(
        hpack(r0.x, r1.x), hpack(r0.y, r1.y), hpack(r0.z, r1.z), hpack(r0.w, r1.w));
}

__global__ __launch_bounds__(256) void repack_v() {
    __shared__ float t[64][68];
    const int nh = blockIdx.y, jt = blockIdx.x, tid = threadIdx.x;
#pragma unroll
    for (int i = 0; i < 4; i++) {
        const int flat = tid + i * 256, tok = flat & 63, d4 = (flat >> 6) * 4;
        *(float4*)&t[tok][d4] = *(const float4*)&g_v[nh][jt * 64 + tok][d4];
    }
    __syncthreads();
    const int jp = tid & 31, dg = tid >> 5;
#pragma unroll
    for (int i = 0; i < 8; i++) {
        const int d = dg * 8 + i;
        g_v16[nh][d][jt * 32 + jp] = hpack(t[2 * jp][d], t[2 * jp + 1][d]);
    }
}

// ---------------- GEMM: k16, 2-buf, LDG+STS, 2-term fp16 ----------------
// smem words: A [buf][hl][128][12] = 6144, B [buf][8 kp][136] = 2176 -> 8320 (33KB)
#define AW(b,hl) (((b)*2+(hl))*1536)
#define BW(b)    (6144 + (b)*1088)

template<int MODE>
__global__ __launch_bounds__(256, 2) void gemm_mma(
    const float* __restrict__ xq, const float* __restrict__ xk, const float* __restrict__ xv,
    const float* __restrict__ bq, const float* __restrict__ bk,
    const float* __restrict__ bv, const float* __restrict__ bp,
    float* __restrict__ outp)
{
    __shared__ uint32_t gsm[8320];
    const uint32_t sb = smem_u32(gsm);

    const int tid = threadIdx.x, wid = tid >> 5, lane = tid & 31;
    const int gid = lane >> 2, tig = lane & 3, wm = wid >> 2, wn = wid & 3;
    const int m0 = blockIdx.x * 128, by = blockIdx.y;
    const int z = (MODE == 0) ? blockIdx.z : 3;

    const float* Xf = (z == 0) ? xq : (z == 1) ? xk : xv;
    const uint32_t* Bw = &g_wb16[z][0][0];
    const float* bias = (z == 0) ? bq : (z == 1) ? bk : (z == 2) ? bv : bp;

    const int ar = tid >> 1, t1 = tid & 1;
    const int bkk = tid >> 5, bn4 = (tid & 31) << 2;
    const int bcol = by * 128 + bn4;

    float acc[4][4][4] = {};
    uint32_t h4[4], l4[4];
    uint4 bh4;

    // ---- chunk 0 ----
    if constexpr (MODE == 0) {
        float4 a0 = *(const float4*)(Xf + (size_t)(m0 + ar) * DIN_ + t1 * 8);
        float4 a1 = *(const float4*)(Xf + (size_t)(m0 + ar) * DIN_ + t1 * 8 + 4);
        hsplit(a0.x, a0.y, h4[0], l4[0]);
        hsplit(a0.z, a0.w, h4[1], l4[1]);
        hsplit(a1.x, a1.y, h4[2], l4[2]);
        hsplit(a1.z, a1.w, h4[3], l4[3]);
    } else {
        uint4 p0 = *(const uint4*)&g_yah[m0 + ar][t1 * 4];
        uint4 p1 = *(const uint4*)&g_yal[m0 + ar][t1 * 4];
        h4[0] = p0.x; h4[1] = p0.y; h4[2] = p0.z; h4[3] = p0.w;
        l4[0] = p1.x; l4[1] = p1.y; l4[2] = p1.z; l4[3] = p1.w;
    }
    bh4 = *(const uint4*)&Bw[(size_t)bkk * 1024 + bcol];

    *(uint4*)&gsm[AW(0,0) + ar * 12 + t1 * 4] = make_uint4(h4[0], h4[1], h4[2], h4[3]);
    *(uint4*)&gsm[AW(0,1) + ar * 12 + t1 * 4] = make_uint4(l4[0], l4[1], l4[2], l4[3]);
    *(uint4*)&gsm[BW(0) + bkk * 136 + bn4] = bh4;
    __syncthreads();

    for (int c = 0; c < 64; c++) {
        const int buf = c & 1;

        if (c < 63) {
            const int kp0 = (c + 1) * 8;
            if constexpr (MODE == 0) {
                float4 a0 = *(const float4*)(Xf + (size_t)(m0 + ar) * DIN_ + kp0 * 2 + t1 * 8);
                float4 a1 = *(const float4*)(Xf + (size_t)(m0 + ar) * DIN_ + kp0 * 2 + t1 * 8 + 4);
                hsplit(a0.x, a0.y, h4[0], l4[0]);
                hsplit(a0.z, a0.w, h4[1], l4[1]);
                hsplit(a1.x, a1.y, h4[2], l4[2]);
                hsplit(a1.z, a1.w, h4[3], l4[3]);
            } else {
                uint4 p0 = *(const uint4*)&g_yah[m0 + ar][kp0 + t1 * 4];
                uint4 p1 = *(const uint4*)&g_yal[m0 + ar][kp0 + t1 * 4];
                h4[0] = p0.x; h4[1] = p0.y; h4[2] = p0.z; h4[3] = p0.w;
                l4[0] = p1.x; l4[1] = p1.y; l4[2] = p1.z; l4[3] = p1.w;
            }
            bh4 = *(const uint4*)&Bw[(size_t)(kp0 + bkk) * 1024 + bcol];
        }

        uint32_t ah[4][4], al[4][4];
#pragma unroll
        for (int mt = 0; mt < 4; mt++) {
            const uint32_t off = (wm * 64 + mt * 16 + (lane & 15)) * 12 + (lane >> 4) * 4;
            ldm4(ah[mt], sb + (AW(buf,0) + off) * 4);
            ldm4(al[mt], sb + (AW(buf,1) + off) * 4);
        }
        uint32_t bf[4][2];
#pragma unroll
        for (int nt = 0; nt < 4; nt++) {
            const int nc = wn * 32 + nt * 8 + gid;
            bf[nt][0] = gsm[BW(buf) + tig * 136 + nc];
            bf[nt][1] = gsm[BW(buf) + (tig + 4) * 136 + nc];
        }
#pragma unroll
        for (int mt = 0; mt < 4; mt++)
#pragma unroll
            for (int nt = 0; nt < 4; nt++)
                mma_fp16(acc[mt][nt], ah[mt], bf[nt]);
#pragma unroll
        for (int mt = 0; mt < 4; mt++)
#pragma unroll
            for (int nt = 0; nt < 4; nt++)
                mma_fp16(acc[mt][nt], al[mt], bf[nt]);

        if (c < 63) {
            const int nb = buf ^ 1;
            *(uint4*)&gsm[AW(nb,0) + ar * 12 + t1 * 4] = make_uint4(h4[0], h4[1], h4[2], h4[3]);
            *(uint4*)&gsm[AW(nb,1) + ar * 12 + t1 * 4] = make_uint4(l4[0], l4[1], l4[2], l4[3]);
            *(uint4*)&gsm[BW(nb) + bkk * 136 + bn4] = bh4;
            __syncthreads();
        }
    }

    // ---- epilogue ----
#pragma unroll
    for (int mt = 0; mt < 4; mt++)
#pragma unroll
        for (int nt = 0; nt < 4; nt++) {
            const int ng = by * 128 + wn * 32 + nt * 8 + 2 * tig;
            const float b0 = bias[ng], b1 = bias[ng + 1];
#pragma unroll
            for (int half = 0; half < 2; half++) {
                const int m = m0 + wm * 64 + mt * 16 + gid + half * 8;
                float v0 = acc[mt][nt][half * 2 + 0] + b0;
                float v1 = acc[mt][nt][half * 2 + 1] + b1;
                if constexpr (MODE == 1) {
                    *(float2*)(outp + (size_t)m * HD_ + ng) = make_float2(v0, v1);
                } else {
                    const int nn = m >> 11, kk = m & 2047, h = ng >> 6;
                    const int dp = (ng >> 1) & 31;
                    if (z == 2) {
                        *(float2*)&g_v[nn * 16 + h][kk][ng & 63] = make_float2(v0, v1);
                    } else if (z == 1) {
                        g_kp16[nn * 16 + h][kk][dp] = hpack(v0, v1);
                    } else {
                        uint32_t hh, ll;
                        hsplit(v0 * QSCALE, v1 * QSCALE, hh, ll);
                        g_qph[nn * 16 + h][kk][dp] = hh;
                        g_qpl[nn * 16 + h][kk][dp] = ll;
                    }
                }
            }
        }
}

// ---------------- flash attention: fp16 2-term, cp.async 2-buf ----------------
// per-buf words: K[64][36]=2304, V[64][36]=2304 -> FBUF 4608; 2 bufs = 36KB
#define FBUF 4608
#define FLASH_SMEM (2 * FBUF * 4)

__global__ __launch_bounds__(256, 2) void flash_mma()
{
    extern __shared__ uint32_t sm[];
    const uint32_t sb = smem_u32(sm);

    const int qt = blockIdx.x, nh = blockIdx.y, n = nh >> 4, h = nh & 15;
    const int tid = threadIdx.x, w = tid >> 5, lane = tid & 31;
    const int gid = lane >> 2, tig = lane & 3, r0 = w * 16 + gid;

    // ---- stage Q planes (cp.async: Qh@0, Ql@4608) ----
    {
        const int qr = tid >> 1, qc = (tid & 1) * 16;
        const uint32_t dq = sb + (qr * 36 + qc) * 4;
#pragma unroll
        for (int i = 0; i < 4; i++) {
            cpa(dq + i * 16,            &g_qph[nh][qt * 128 + qr][qc + i * 4]);
            cpa(dq + 4608 * 4 + i * 16, &g_qpl[nh][qt * 128 + qr][qc + i * 4]);
        }
        CP_COMMIT();
    }
    CP_WAIT0();
    __syncthreads();

    uint32_t afh[4][4], afl[4][4];
    {
        const uint32_t off = (uint32_t)(w * 16 + (lane & 15)) * 36 + (lane >> 4) * 4;
#pragma unroll
        for (int sp = 0; sp < 4; sp++) {
            ldm4(afh[sp], sb + (off + sp * 8) * 4);
            ldm4(afl[sp], sb + (4608 + off + sp * 8) * 4);
        }
    }
    __syncthreads();   // Q staging consumed before tile0 overwrite

    const int fj = tid >> 2, fq = (tid & 3) * 8;
    const uint32_t dK = sb + (fj * 36 + fq) * 4;
    const uint32_t dV = sb + (2304 + fj * 36 + fq) * 4;

#define FCP(kt, buf) do { \
    cpa(dK + (buf) * FBUF * 4,      &g_kp16[nh][(kt) * 64 + fj][fq]); \
    cpa(dK + (buf) * FBUF * 4 + 16, &g_kp16[nh][(kt) * 64 + fj][fq + 4]); \
    cpa(dV + (buf) * FBUF * 4,      &g_v16[nh][fj][(kt) * 32 + fq]); \
    cpa(dV + (buf) * FBUF * 4 + 16, &g_v16[nh][fj][(kt) * 32 + fq + 4]); \
    CP_COMMIT(); } while (0)

    FCP(0, 0);

    float o[8][4] = {};
    float ls0 = 0.f, ls1 = 0.f;
    const uint32_t* mr0 = g_mb + (size_t)(n * K_ + qt * 128 + r0) * 64;
    const uint32_t* mr1 = mr0 + 8 * 64;

    const uint32_t brow = (lane & 7) + ((lane & 16) ? 8u : 0u);
    const uint32_t bbyt = (lane & 8) ? 16u : 0u;

#pragma unroll 2
    for (int kt = 0; kt < 32; kt++) {
        const int buf = kt & 1;
        const uint2 w0 = *(const uint2*)(mr0 + kt * 2);
        const uint2 w1 = *(const uint2*)(mr1 + kt * 2);
        CP_WAIT0();
        __syncthreads();
        if (kt + 1 < 32) { FCP(kt + 1, buf ^ 1); } else { CP_COMMIT(); }

        // S = Q K^T  (2-term: (qh+ql)·k16)
        float s[8][4] = {};
#pragma unroll
        for (int sp = 0; sp < 4; sp++) {
#pragma unroll
            for (int g = 0; g < 4; g++) {
                const uint32_t base = (buf * FBUF + (g * 16 + brow) * 36 + sp * 8) * 4 + bbyt;
                uint32_t k4[4];
                ldm4(k4, sb + base);
                mma_fp16(s[g * 2 + 0], afh[sp], k4);
                mma_fp16(s[g * 2 + 1], afh[sp], k4 + 2);
                mma_fp16(s[g * 2 + 0], afl[sp], k4);
                mma_fp16(s[g * 2 + 1], afl[sp], k4 + 2);
            }
        }

        // mask + exp2 (no-max softmax; scale in q, bias -8 cancels in normalization)
#pragma unroll
        for (int nt = 0; nt < 8; nt++) {
            const int jb = nt * 8 + 2 * tig;
#pragma unroll
            for (int cc = 0; cc < 4; cc++) {
                const int j = jb + (cc & 1);
                const uint32_t word = (cc < 2) ? ((j < 32) ? w0.x : w0.y)
                                               : ((j < 32) ? w1.x : w1.y);
                s[nt][cc] = ((word >> (j & 31)) & 1u) ? 0.f : ex2f(s[nt][cc] - PBIAS);
            }
            ls0 += s[nt][0] + s[nt][1];
            ls1 += s[nt][2] + s[nt][3];
        }

        // O += P V  (2-term: (ph+pl)·v16)
#pragma unroll
        for (int sp = 0; sp < 4; sp++) {
            uint32_t aph[4], apl[4];
            hsplit(s[2 * sp][0],     s[2 * sp][1],     aph[0], apl[0]);
            hsplit(s[2 * sp][2],     s[2 * sp][3],     aph[1], apl[1]);
            hsplit(s[2 * sp + 1][0], s[2 * sp + 1][1], aph[2], apl[2]);
            hsplit(s[2 * sp + 1][2], s[2 * sp + 1][3], aph[3], apl[3]);
#pragma unroll
            for (int g = 0; g < 4; g++) {
                const uint32_t base = (buf * FBUF + 2304 + (g * 16 + brow) * 36 + sp * 8) * 4 + bbyt;
                uint32_t v4[4];
                ldm4(v4, sb + base);
                mma_fp16(o[g * 2 + 0], aph, v4);
                mma_fp16(o[g * 2 + 1], aph, v4 + 2);
                mma_fp16(o[g * 2 + 0], apl, v4);
                mma_fp16(o[g * 2 + 1], apl, v4 + 2);
            }
        }
    }

    // epilogue
    ls0 += __shfl_xor_sync(0xffffffffu, ls0, 1);
    ls0 += __shfl_xor_sync(0xffffffffu, ls0, 2);
    ls1 += __shfl_xor_sync(0xffffffffu, ls1, 1);
    ls1 += __shfl_xor_sync(0xffffffffu, ls1, 2);
    const float i0 = 1.0f / ls0, i1 = 1.0f / ls1;
    const int row = n * K_ + qt * 128 + r0;
#pragma unroll
    for (int dn = 0; dn < 8; dn++) {
        const int dp = h * 32 + dn * 4 + tig;
        uint32_t hh, ll;
        hsplit(o[dn][0] * i0, o[dn][1] * i0, hh, ll);
        g_yah[row][dp] = hh;  g_yal[row][dp] = ll;
        hsplit(o[dn][2] * i1, o[dn][3] * i1, hh, ll);
        g_yah[row + 8][dp] = hh;  g_yal[row + 8][dp] = ll;
    }
}

// ---------------- launch ----------------
extern "C" void kernel_launch(void* const* d_in, const int* in_sizes, int n_in,
                              void* d_out, int out_size)
{
    const float* query = (const float*)d_in[0];
    const float* key   = (const float*)d_in[1];
    const float* value = (const float*)d_in[2];
    const int*   mask  = (const int*)d_in[3];
    const float* Wq = (const float*)d_in[4];
    const float* bq = (const float*)d_in[5];
    const float* Wk = (const float*)d_in[6];
    const float* bk = (const float*)d_in[7];
    const float* Wv = (const float*)d_in[8];
    const float* bv = (const float*)d_in[9];
    const float* Wp = (const float*)d_in[10];
    const float* bp = (const float*)d_in[11];
    float* out = (float*)d_out;

    cudaFuncSetAttribute(flash_mma, cudaFuncAttributeMaxDynamicSharedMemorySize, FLASH_SMEM);

    mask_pack<<<(N_ * K_ * K_) / 256, 256>>>(mask);
    split_w<<<dim3(512, 4), 256>>>(Wq, Wk, Wv, Wp);
    gemm_mma<0><<<dim3(32, 8, 3), 256>>>(query, key, value, bq, bk, bv, bp, nullptr);
    repack_v<<<dim3(32, 32), 256>>>();
    flash_mma<<<dim3(16, 32), 256, FLASH_SMEM>>>();
    gemm_mma<1><<<dim3(32, 8, 1), 256>>>(nullptr, nullptr, nullptr, bq, bk, bv, bp, out);
}